// round 1
// baseline (speedup 1.0000x reference)
#include <cuda_runtime.h>

#define NN 100000
#define NE 1600000
#define DD 128
#define NP 500000

// ---- scratch (device globals; no allocation allowed) ----
__device__ __align__(16) float g_x[NN * DD];      // layer input / final h
__device__ __align__(16) float g_h[NN * DD];      // layer1 output
__device__ __align__(16) float g_xnorm[NN * DD];
__device__ __align__(16) float g_agg[NN * DD];
__device__ int g_deg_s[NN];
__device__ int g_deg_r[NN];
__device__ int g_rowstart[NN + 1];
__device__ int g_cursor[NN];
__device__ int g_esrc[NE];

__device__ __forceinline__ float4 f4add(float4 a, float4 b) {
    return make_float4(a.x + b.x, a.y + b.y, a.z + b.z, a.w + b.w);
}

// ---------------------------------------------------------------------------
__global__ void k_init_deg() {
    int i = blockIdx.x * blockDim.x + threadIdx.x;
    if (i < NN) { g_deg_s[i] = 1; g_deg_r[i] = 1; }   // self-loop counts
}

__global__ void k_count(const int* __restrict__ senders, const int* __restrict__ receivers) {
    int stride = gridDim.x * blockDim.x;
    for (int e = blockIdx.x * blockDim.x + threadIdx.x; e < NE; e += stride) {
        atomicAdd(&g_deg_s[senders[e]], 1);
        atomicAdd(&g_deg_r[receivers[e]], 1);
    }
}

// single-block exclusive scan of in-degrees (excluding self-loop) -> rowstart/cursor
__global__ void k_scan() {
    __shared__ int ss[1024];
    int t = threadIdx.x;
    const int chunk = (NN + 1023) / 1024;   // 98
    int beg = t * chunk;
    int end = beg + chunk; if (end > NN) end = NN;
    int s = 0;
    for (int i = beg; i < end; i++) s += g_deg_r[i] - 1;
    ss[t] = s;
    __syncthreads();
    for (int off = 1; off < 1024; off <<= 1) {
        int v = (t >= off) ? ss[t - off] : 0;
        __syncthreads();
        ss[t] += v;
        __syncthreads();
    }
    int run = (t == 0) ? 0 : ss[t - 1];
    for (int i = beg; i < end; i++) {
        g_rowstart[i] = run;
        g_cursor[i] = run;
        run += g_deg_r[i] - 1;
    }
    if (t == 0) g_rowstart[NN] = ss[1023];
}

__global__ void k_scatter(const int* __restrict__ senders, const int* __restrict__ receivers) {
    int stride = gridDim.x * blockDim.x;
    for (int e = blockIdx.x * blockDim.x + threadIdx.x; e < NE; e += stride) {
        int r = receivers[e];
        int pos = atomicAdd(&g_cursor[r], 1);
        g_esrc[pos] = senders[e];
    }
}

__global__ void k_gather_x0(const int* __restrict__ node_ids, const float* __restrict__ emb) {
    int i = blockIdx.x * blockDim.x + threadIdx.x;   // over NN*32 float4s
    if (i < NN * (DD / 4)) {
        int node = i >> 5;
        int q = i & 31;
        int src = node_ids[node];
        ((float4*)g_x)[i] = ((const float4*)emb)[src * 32 + q];
    }
}

__global__ void k_xnorm(const float* __restrict__ xin) {
    int i = blockIdx.x * blockDim.x + threadIdx.x;
    if (i < NN * (DD / 4)) {
        int node = i >> 5;
        float sc = rsqrtf((float)g_deg_s[node]);
        float4 v = ((const float4*)xin)[i];
        v.x *= sc; v.y *= sc; v.z *= sc; v.w *= sc;
        ((float4*)g_xnorm)[i] = v;
    }
}

// one warp per node: acc = xnorm[self] + sum_{in-edges} xnorm[src]; scale cnt^-1.5
__global__ void k_aggregate() {
    int gw = (blockIdx.x * blockDim.x + threadIdx.x) >> 5;
    if (gw >= NN) return;
    int lane = threadIdx.x & 31;
    const float4* __restrict__ xn = (const float4*)g_xnorm;
    float4 acc = xn[gw * 32 + lane];     // self-loop message
    int s = g_rowstart[gw], e = g_rowstart[gw + 1];
    int j = s;
    for (; j + 4 <= e; j += 4) {
        int s0 = g_esrc[j], s1 = g_esrc[j + 1], s2 = g_esrc[j + 2], s3 = g_esrc[j + 3];
        float4 a0 = xn[s0 * 32 + lane];
        float4 a1 = xn[s1 * 32 + lane];
        float4 a2 = xn[s2 * 32 + lane];
        float4 a3 = xn[s3 * 32 + lane];
        acc = f4add(acc, f4add(f4add(a0, a1), f4add(a2, a3)));
    }
    for (; j < e; j++) acc = f4add(acc, xn[g_esrc[j] * 32 + lane]);
    float cnt = (float)(e - s + 1);
    float sc = rsqrtf(cnt) / cnt;        // cnt^-1.5
    acc.x *= sc; acc.y *= sc; acc.z *= sc; acc.w *= sc;
    ((float4*)g_agg)[gw * 32 + lane] = acc;
}

// C[row][0..128) = act( [X|A][row] @ W[256x128] + b ),  BM=64, BN=128, BK=16
template <bool RELU>
__global__ void __launch_bounds__(256) k_gemm(
    const float* __restrict__ X, const float* __restrict__ A,
    const float* __restrict__ W, const float* __restrict__ b,
    float* __restrict__ C, int M)
{
    __shared__ float As[16][64];
    __shared__ float Bs[16][128];
    int tid = threadIdx.x;
    int tx = tid & 31;          // col group (4 cols each)
    int ty = tid >> 5;          // row group (8 rows each)
    int block_row = blockIdx.x * 64;

    float acc[8][4];
#pragma unroll
    for (int m = 0; m < 8; m++)
#pragma unroll
        for (int n = 0; n < 4; n++) acc[m][n] = 0.f;

    int ar = tid >> 2, aq = tid & 3;
    int arow = block_row + ar;
    int arow_c = arow < M ? arow : M - 1;

    for (int kb = 0; kb < 256; kb += 16) {
        const float* src = (kb < 128) ? X : A;
        int koff = kb & 127;
        float4 av = ((const float4*)(src + arow_c * DD + koff))[aq];
        As[aq * 4 + 0][ar] = av.x;
        As[aq * 4 + 1][ar] = av.y;
        As[aq * 4 + 2][ar] = av.z;
        As[aq * 4 + 3][ar] = av.w;
#pragma unroll
        for (int l = 0; l < 2; l++) {
            int f = tid + l * 256;
            int kk = f >> 5, c4 = f & 31;
            ((float4*)&Bs[kk][0])[c4] = ((const float4*)(W + (kb + kk) * DD))[c4];
        }
        __syncthreads();
#pragma unroll
        for (int kk = 0; kk < 16; kk++) {
            float4 bv = ((const float4*)&Bs[kk][0])[tx];
            float a[8];
#pragma unroll
            for (int m = 0; m < 8; m++) a[m] = As[kk][ty * 8 + m];
#pragma unroll
            for (int m = 0; m < 8; m++) {
                acc[m][0] += a[m] * bv.x;
                acc[m][1] += a[m] * bv.y;
                acc[m][2] += a[m] * bv.z;
                acc[m][3] += a[m] * bv.w;
            }
        }
        __syncthreads();
    }

    float4 bias = ((const float4*)b)[tx];
#pragma unroll
    for (int m = 0; m < 8; m++) {
        int row = block_row + ty * 8 + m;
        if (row < M) {
            float4 v;
            v.x = acc[m][0] + bias.x;
            v.y = acc[m][1] + bias.y;
            v.z = acc[m][2] + bias.z;
            v.w = acc[m][3] + bias.w;
            if (RELU) {
                v.x = fmaxf(v.x, 0.f); v.y = fmaxf(v.y, 0.f);
                v.z = fmaxf(v.z, 0.f); v.w = fmaxf(v.w, 0.f);
            }
            ((float4*)(C + row * DD))[tx] = v;
        }
    }
}

// link predictor: per pair p, z = h[a]*h[b]; score = relu(z@Wa+ba)@Wb + bb
__global__ void __launch_bounds__(256) k_linkpred(
    const float* __restrict__ H, const int* __restrict__ pairs,
    const float* __restrict__ Wa, const float* __restrict__ ba,
    const float* __restrict__ Wb, const float* __restrict__ bb,
    float* __restrict__ out)
{
    __shared__ float As[16][64];
    __shared__ float Bs[16][128];
    int tid = threadIdx.x;
    int tx = tid & 31;
    int ty = tid >> 5;
    int bp = blockIdx.x * 64;

    float acc[8][4];
#pragma unroll
    for (int m = 0; m < 8; m++)
#pragma unroll
        for (int n = 0; n < 4; n++) acc[m][n] = 0.f;

    int ar = tid >> 2, aq = tid & 3;
    int prow = bp + ar;
    int pc = prow < NP ? prow : NP - 1;
    int ia = pairs[2 * pc];
    int ib = pairs[2 * pc + 1];

    for (int kb = 0; kb < 128; kb += 16) {
        float4 ha = ((const float4*)(H + ia * DD + kb))[aq];
        float4 hb = ((const float4*)(H + ib * DD + kb))[aq];
        As[aq * 4 + 0][ar] = ha.x * hb.x;
        As[aq * 4 + 1][ar] = ha.y * hb.y;
        As[aq * 4 + 2][ar] = ha.z * hb.z;
        As[aq * 4 + 3][ar] = ha.w * hb.w;
#pragma unroll
        for (int l = 0; l < 2; l++) {
            int f = tid + l * 256;
            int kk = f >> 5, c4 = f & 31;
            ((float4*)&Bs[kk][0])[c4] = ((const float4*)(Wa + (kb + kk) * DD))[c4];
        }
        __syncthreads();
#pragma unroll
        for (int kk = 0; kk < 16; kk++) {
            float4 bv = ((const float4*)&Bs[kk][0])[tx];
            float a[8];
#pragma unroll
            for (int m = 0; m < 8; m++) a[m] = As[kk][ty * 8 + m];
#pragma unroll
            for (int m = 0; m < 8; m++) {
                acc[m][0] += a[m] * bv.x;
                acc[m][1] += a[m] * bv.y;
                acc[m][2] += a[m] * bv.z;
                acc[m][3] += a[m] * bv.w;
            }
        }
        __syncthreads();
    }

    float4 bav = ((const float4*)ba)[tx];
    float4 wbv = ((const float4*)Wb)[tx];
    float bbv = bb[0];
#pragma unroll
    for (int m = 0; m < 8; m++) {
        float v = fmaxf(acc[m][0] + bav.x, 0.f) * wbv.x
                + fmaxf(acc[m][1] + bav.y, 0.f) * wbv.y
                + fmaxf(acc[m][2] + bav.z, 0.f) * wbv.z
                + fmaxf(acc[m][3] + bav.w, 0.f) * wbv.w;
#pragma unroll
        for (int off = 16; off > 0; off >>= 1)
            v += __shfl_xor_sync(0xffffffffu, v, off);
        if (tx == 0) {
            int row = bp + ty * 8 + m;
            if (row < NP) out[row] = v + bbv;
        }
    }
}

// ---------------------------------------------------------------------------
extern "C" void kernel_launch(void* const* d_in, const int* in_sizes, int n_in,
                              void* d_out, int out_size) {
    const int*   node_ids  = (const int*)d_in[0];
    const int*   senders   = (const int*)d_in[1];
    const int*   receivers = (const int*)d_in[2];
    const int*   pairs     = (const int*)d_in[3];
    const float* emb       = (const float*)d_in[4];
    const float* W1        = (const float*)d_in[5];
    const float* b1        = (const float*)d_in[6];
    const float* W2        = (const float*)d_in[7];
    const float* b2        = (const float*)d_in[8];
    const float* Wa        = (const float*)d_in[9];
    const float* ba        = (const float*)d_in[10];
    const float* Wb        = (const float*)d_in[11];
    const float* bb        = (const float*)d_in[12];
    float* out = (float*)d_out;

    float *x, *h, *ag;
    cudaGetSymbolAddress((void**)&x,  g_x);
    cudaGetSymbolAddress((void**)&h,  g_h);
    cudaGetSymbolAddress((void**)&ag, g_agg);

    const int elem4 = NN * (DD / 4);           // 3.2M float4
    const int vb = (elem4 + 255) / 256;        // 12500

    k_init_deg<<<(NN + 255) / 256, 256>>>();
    k_count<<<2048, 256>>>(senders, receivers);
    k_scan<<<1, 1024>>>();
    k_scatter<<<2048, 256>>>(senders, receivers);
    k_gather_x0<<<vb, 256>>>(node_ids, emb);

    // layer 1: x -> h (relu)
    k_xnorm<<<vb, 256>>>(x);
    k_aggregate<<<vb, 256>>>();
    k_gemm<true><<<(NN + 63) / 64, 256>>>(x, ag, W1, b1, h, NN);

    // layer 2: h -> x (no relu)
    k_xnorm<<<vb, 256>>>(h);
    k_aggregate<<<vb, 256>>>();
    k_gemm<false><<<(NN + 63) / 64, 256>>>(h, ag, W2, b2, x, NN);

    // link predictor
    k_linkpred<<<(NP + 63) / 64, 256>>>(x, pairs, Wa, ba, Wb, bb, out);
}